// round 6
// baseline (speedup 1.0000x reference)
#include <cuda_runtime.h>

#define GRIDN 256
#define STEP  (1.0f / 255.0f)
#define NQMAX 4194304
#define NBINS 65536          // (i0, i1) bins
#define NPART 64             // NBINS / 1024

// Scratch (device globals: allocation-free per harness rules).
__device__ unsigned int g_offs[NBINS];   // hist, then within-chunk exclusive offsets
__device__ unsigned int g_part[NPART];   // chunk base offsets
__device__ float4       g_sorted[NQMAX];

// Exact bracket (reference searchsorted-right semantics) for p[i] = i*STEP.
__device__ __forceinline__ void bracketA(float x, int& il, int& ir,
                                         float& dl, float& dr)
{
    int g = (int)floorf(x * 255.0f) + 1;
    g = max(0, min(g, GRIDN));
    while (g < GRIDN && (float)g * STEP <= x) g++;
    while (g > 0 && (float)(g - 1) * STEP > x) g--;
    ir = min(g, GRIDN - 1);
    il = max(ir - 1, 0);
    dl = fmaxf(x - (float)il * STEP, 0.0f);
    dr = fmaxf((float)ir * STEP - x, 0.0f);
    if (dl == 0.0f && dr == 0.0f) { dl = 1.0f; dr = 1.0f; }
}

// Cheap approximate cell for binning only (locality, not correctness).
__device__ __forceinline__ int cellFast(float x)
{
    return max(0, min(254, (int)floorf(x * 255.0f)));
}

__device__ __forceinline__ int binKey(float a, float b)
{
    return (cellFast(a) << 8) | cellFast(b);
}

// ---------------- pass kernels ----------------

__global__ void k_zero()
{
    int i = blockIdx.x * blockDim.x + threadIdx.x;
    if (i < NBINS) g_offs[i] = 0u;
}

__global__ void k_hist(const float* __restrict__ x0, const float* __restrict__ x1,
                       int n)
{
    int i = blockIdx.x * blockDim.x + threadIdx.x;
    if (i >= n) return;
    atomicAdd(&g_offs[binKey(x0[i], x1[i])], 1u);
}

// Scan 1024-bin chunks; g_offs becomes within-chunk EXCLUSIVE offsets,
// g_part gets chunk totals.
__global__ void k_scan1()
{
    __shared__ unsigned int s[1024];
    int t = threadIdx.x;
    int base = blockIdx.x * 1024;
    unsigned int v = g_offs[base + t];
    s[t] = v;
    __syncthreads();
    for (int o = 1; o < 1024; o <<= 1) {
        unsigned int a = (t >= o) ? s[t - o] : 0u;
        __syncthreads();
        s[t] += a;
        __syncthreads();
    }
    g_offs[base + t] = s[t] - v;
    if (t == 1023) g_part[blockIdx.x] = s[t];
}

// Exclusive scan of the 64 chunk totals (single warp-ish block).
__global__ void k_scan2()
{
    __shared__ unsigned int s[NPART];
    int t = threadIdx.x;
    unsigned int v = g_part[t];
    s[t] = v;
    __syncthreads();
    for (int o = 1; o < NPART; o <<= 1) {
        unsigned int a = (t >= o) ? s[t - o] : 0u;
        __syncthreads();
        s[t] += a;
        __syncthreads();
    }
    g_part[t] = s[t] - v;   // exclusive chunk base
}

__global__ void k_scatter(const float* __restrict__ x0, const float* __restrict__ x1,
                          const float* __restrict__ x2, int n)
{
    int i = blockIdx.x * blockDim.x + threadIdx.x;
    if (i >= n) return;
    float a = x0[i], b = x1[i], c = x2[i];
    int k = binKey(a, b);
    unsigned int p = g_part[k >> 10] + atomicAdd(&g_offs[k], 1u);
    g_sorted[p] = make_float4(a, b, c, __int_as_float(i));
}

__global__ __launch_bounds__(256)
void k_process(const float* __restrict__ values, float* __restrict__ out, int n)
{
    int i = blockIdx.x * blockDim.x + threadIdx.x;
    if (i >= n) return;
    float4 q = g_sorted[i];
    int orig = __float_as_int(q.w);

    int il0, ir0, il1, ir1, il2, ir2;
    float dl0, dr0, dl1, dr1, dl2, dr2;
    bracketA(q.x, il0, ir0, dl0, dr0);
    bracketA(q.y, il1, ir1, dl1, dr1);
    bracketA(q.z, il2, ir2, dl2, dr2);

    long bll = ((long)il0 * GRIDN + il1) * GRIDN;
    long blr = ((long)il0 * GRIDN + ir1) * GRIDN;
    long brl = ((long)ir0 * GRIDN + il1) * GRIDN;
    long brr = ((long)ir0 * GRIDN + ir1) * GRIDN;

    float v000 = __ldg(values + bll + il2);
    float v001 = __ldg(values + bll + ir2);
    float v010 = __ldg(values + blr + il2);
    float v011 = __ldg(values + blr + ir2);
    float v100 = __ldg(values + brl + il2);
    float v101 = __ldg(values + brl + ir2);
    float v110 = __ldg(values + brr + il2);
    float v111 = __ldg(values + brr + ir2);

    float num = 0.0f;
    num = fmaf(v000, dr0 * dr1 * dr2, num);
    num = fmaf(v001, dr0 * dr1 * dl2, num);
    num = fmaf(v010, dr0 * dl1 * dr2, num);
    num = fmaf(v011, dr0 * dl1 * dl2, num);
    num = fmaf(v100, dl0 * dr1 * dr2, num);
    num = fmaf(v101, dl0 * dr1 * dl2, num);
    num = fmaf(v110, dl0 * dl1 * dr2, num);
    num = fmaf(v111, dl0 * dl1 * dl2, num);
    float denom = (dl0 + dr0) * (dl1 + dr1) * (dl2 + dr2);

    out[orig] = num / denom;
}

extern "C" void kernel_launch(void* const* d_in, const int* in_sizes, int n_in,
                              void* d_out, int out_size)
{
    const float* x0 = (const float*)d_in[0];
    const float* x1 = (const float*)d_in[1];
    const float* x2 = (const float*)d_in[2];
    const float* values = (const float*)d_in[6];
    float* out = (float*)d_out;

    int n = in_sizes[0];
    int qb = (n + 255) / 256;

    k_zero   <<<NBINS / 1024, 1024>>>();
    k_hist   <<<qb, 256>>>(x0, x1, n);
    k_scan1  <<<NPART, 1024>>>();
    k_scan2  <<<1, NPART>>>();
    k_scatter<<<qb, 256>>>(x0, x1, x2, n);
    k_process<<<qb, 256>>>(values, out, n);
}

// round 7
// speedup vs baseline: 1.4232x; 1.4232x over previous
#include <cuda_runtime.h>

#define GRIDN 256
#define STEP  (1.0f / 255.0f)
#define NQMAX 4194304
#define NBINS (1 << 21)      // i0:8 | i1:8 | k>>3:5
#define NPART 2048           // NBINS / 1024

// Scratch (device globals: allocation-free per harness rules).
__device__ unsigned int g_hist[NBINS];   // counts -> within-chunk exclusive offsets
__device__ unsigned int g_part[NPART];   // chunk totals -> exclusive chunk bases
__device__ float4       g_sorted[NQMAX];

// Exact bracket (reference searchsorted-right semantics) for p[i] = i*STEP.
__device__ __forceinline__ void bracketA(float x, int& il, int& ir,
                                         float& dl, float& dr)
{
    int g = (int)floorf(x * 255.0f) + 1;
    g = max(0, min(g, GRIDN));
    while (g < GRIDN && (float)g * STEP <= x) g++;
    while (g > 0 && (float)(g - 1) * STEP > x) g--;
    ir = min(g, GRIDN - 1);
    il = max(ir - 1, 0);
    dl = fmaxf(x - (float)il * STEP, 0.0f);
    dr = fmaxf((float)ir * STEP - x, 0.0f);
    if (dl == 0.0f && dr == 0.0f) { dl = 1.0f; dr = 1.0f; }
}

// Cheap cell estimate for BINNING ONLY (no fix-up loops; locality not correctness).
__device__ __forceinline__ int cellFast(float x)
{
    return max(0, min(254, (int)floorf(x * 255.0f)));
}

__device__ __forceinline__ int binKey(float a, float b, float c)
{
    return (cellFast(a) << 13) | (cellFast(b) << 5) | (cellFast(c) >> 3);
}

// ---------------- pass kernels ----------------

__global__ void k_zero()
{
    int i = blockIdx.x * blockDim.x + threadIdx.x;
    if (i < NBINS) g_hist[i] = 0u;
}

__global__ void k_hist(const float* __restrict__ x0, const float* __restrict__ x1,
                       const float* __restrict__ x2, int n)
{
    int i = blockIdx.x * blockDim.x + threadIdx.x;
    if (i >= n) return;
    atomicAdd(&g_hist[binKey(x0[i], x1[i], x2[i])], 1u);
}

// Warp-shuffle block scan: 1024 bins/block. g_hist becomes within-chunk
// EXCLUSIVE offsets; g_part[b] gets the chunk total.
__global__ void k_scan1()
{
    __shared__ unsigned int wsum[32];
    int t = threadIdx.x;
    int base = blockIdx.x * 1024;
    unsigned int v = g_hist[base + t];
    unsigned int s = v;
    #pragma unroll
    for (int o = 1; o < 32; o <<= 1) {
        unsigned int u = __shfl_up_sync(0xFFFFFFFFu, s, o);
        if ((t & 31) >= o) s += u;
    }
    if ((t & 31) == 31) wsum[t >> 5] = s;
    __syncthreads();
    if (t < 32) {
        unsigned int w = wsum[t], sw = w;
        #pragma unroll
        for (int o = 1; o < 32; o <<= 1) {
            unsigned int u = __shfl_up_sync(0xFFFFFFFFu, sw, o);
            if (t >= o) sw += u;
        }
        wsum[t] = sw - w;   // exclusive warp base
    }
    __syncthreads();
    unsigned int excl = (s - v) + wsum[t >> 5];
    g_hist[base + t] = excl;
    if (t == 1023) g_part[blockIdx.x] = excl + v;
}

// Exclusive scan of the 2048 chunk totals (one block, 2 elems/thread).
__global__ void k_scan2()
{
    __shared__ unsigned int wsum[32];
    int t = threadIdx.x;
    unsigned int v0 = g_part[2 * t];
    unsigned int v1 = g_part[2 * t + 1];
    unsigned int pv = v0 + v1;
    unsigned int s = pv;
    #pragma unroll
    for (int o = 1; o < 32; o <<= 1) {
        unsigned int u = __shfl_up_sync(0xFFFFFFFFu, s, o);
        if ((t & 31) >= o) s += u;
    }
    if ((t & 31) == 31) wsum[t >> 5] = s;
    __syncthreads();
    if (t < 32) {
        unsigned int w = wsum[t], sw = w;
        #pragma unroll
        for (int o = 1; o < 32; o <<= 1) {
            unsigned int u = __shfl_up_sync(0xFFFFFFFFu, sw, o);
            if (t >= o) sw += u;
        }
        wsum[t] = sw - w;
    }
    __syncthreads();
    unsigned int excl = (s - pv) + wsum[t >> 5];
    g_part[2 * t]     = excl;
    g_part[2 * t + 1] = excl + v0;
}

__global__ void k_scatter(const float* __restrict__ x0, const float* __restrict__ x1,
                          const float* __restrict__ x2, int n)
{
    int i = blockIdx.x * blockDim.x + threadIdx.x;
    if (i >= n) return;
    float a = x0[i], b = x1[i], c = x2[i];
    int k = binKey(a, b, c);
    unsigned int p = g_part[k >> 10] + atomicAdd(&g_hist[k], 1u);
    g_sorted[p] = make_float4(a, b, c, __int_as_float(i));
}

__global__ __launch_bounds__(256)
void k_process(const float* __restrict__ values, float* __restrict__ out, int n)
{
    int i = blockIdx.x * blockDim.x + threadIdx.x;
    if (i >= n) return;
    float4 q = g_sorted[i];
    int orig = __float_as_int(q.w);

    int il0, ir0, il1, ir1, il2, ir2;
    float dl0, dr0, dl1, dr1, dl2, dr2;
    bracketA(q.x, il0, ir0, dl0, dr0);
    bracketA(q.y, il1, ir1, dl1, dr1);
    bracketA(q.z, il2, ir2, dl2, dr2);

    // 32-bit index math (256^3 < 2^31): cuts ALU pressure vs 64-bit.
    int bll = (il0 * GRIDN + il1) * GRIDN;
    int blr = (il0 * GRIDN + ir1) * GRIDN;
    int brl = (ir0 * GRIDN + il1) * GRIDN;
    int brr = (ir0 * GRIDN + ir1) * GRIDN;

    float v000 = __ldg(values + bll + il2);
    float v001 = __ldg(values + bll + ir2);
    float v010 = __ldg(values + blr + il2);
    float v011 = __ldg(values + blr + ir2);
    float v100 = __ldg(values + brl + il2);
    float v101 = __ldg(values + brl + ir2);
    float v110 = __ldg(values + brr + il2);
    float v111 = __ldg(values + brr + ir2);

    float num = 0.0f;
    num = fmaf(v000, dr0 * dr1 * dr2, num);
    num = fmaf(v001, dr0 * dr1 * dl2, num);
    num = fmaf(v010, dr0 * dl1 * dr2, num);
    num = fmaf(v011, dr0 * dl1 * dl2, num);
    num = fmaf(v100, dl0 * dr1 * dr2, num);
    num = fmaf(v101, dl0 * dr1 * dl2, num);
    num = fmaf(v110, dl0 * dl1 * dr2, num);
    num = fmaf(v111, dl0 * dl1 * dl2, num);
    float denom = (dl0 + dr0) * (dl1 + dr1) * (dl2 + dr2);

    out[orig] = num / denom;
}

extern "C" void kernel_launch(void* const* d_in, const int* in_sizes, int n_in,
                              void* d_out, int out_size)
{
    const float* x0 = (const float*)d_in[0];
    const float* x1 = (const float*)d_in[1];
    const float* x2 = (const float*)d_in[2];
    const float* values = (const float*)d_in[6];
    float* out = (float*)d_out;

    int n = in_sizes[0];
    int qb = (n + 255) / 256;

    k_zero   <<<NBINS / 1024, 1024>>>();
    k_hist   <<<qb, 256>>>(x0, x1, x2, n);
    k_scan1  <<<NPART, 1024>>>();
    k_scan2  <<<1, 1024>>>();
    k_scatter<<<qb, 256>>>(x0, x1, x2, n);
    k_process<<<qb, 256>>>(values, out, n);
}

// round 9
// speedup vs baseline: 1.9439x; 1.3659x over previous
#include <cuda_runtime.h>

#define GRIDN 256
#define STEP  (1.0f / 255.0f)

// Exact bracket (reference searchsorted-right + clamp/distance semantics)
// for the linspace grid p[i] = i*STEP. Pure ALU/FMA, no memory.
__device__ __forceinline__ void bracketA(float x, int& il, int& ir,
                                         float& dl, float& dr)
{
    int g = (int)floorf(x * 255.0f) + 1;
    g = max(0, min(g, GRIDN));
    while (g < GRIDN && (float)g * STEP <= x) g++;
    while (g > 0 && (float)(g - 1) * STEP > x) g--;
    ir = min(g, GRIDN - 1);
    il = max(ir - 1, 0);
    dl = fmaxf(x - (float)il * STEP, 0.0f);
    dr = fmaxf((float)ir * STEP - x, 0.0f);
    if (dl == 0.0f && dr == 0.0f) { dl = 1.0f; dr = 1.0f; }
}

__global__ __launch_bounds__(256)
void rgi_kernel(const float* __restrict__ x0, const float* __restrict__ x1,
                const float* __restrict__ x2,
                const float* __restrict__ values,
                float* __restrict__ out, int n)
{
    int i = blockIdx.x * blockDim.x + threadIdx.x;
    if (i >= n) return;

    float q0 = __ldg(x0 + i);
    float q1 = __ldg(x1 + i);
    float q2 = __ldg(x2 + i);

    int il0, ir0, il1, ir1, il2, ir2;
    float dl0, dr0, dl1, dr1, dl2, dr2;
    bracketA(q0, il0, ir0, dl0, dr0);
    bracketA(q1, il1, ir1, dl1, dr1);
    bracketA(q2, il2, ir2, dl2, dr2);

    // 32-bit index math (256^3 < 2^31).
    int bll = (il0 * GRIDN + il1) * GRIDN;
    int blr = (il0 * GRIDN + ir1) * GRIDN;
    int brl = (ir0 * GRIDN + il1) * GRIDN;
    int brr = (ir0 * GRIDN + ir1) * GRIDN;

    // 8 independent gathers, L2-only (no L1 allocate: fills are never reused;
    // k-pair sector sharing is merged in the MSHR anyway).
    float v000 = __ldcg(values + bll + il2);
    float v001 = __ldcg(values + bll + ir2);
    float v010 = __ldcg(values + blr + il2);
    float v011 = __ldcg(values + blr + ir2);
    float v100 = __ldcg(values + brl + il2);
    float v101 = __ldcg(values + brl + ir2);
    float v110 = __ldcg(values + brr + il2);
    float v111 = __ldcg(values + brr + ir2);

    // Corner weight = product of OPPOSITE-side distances (reference semantics).
    float num = 0.0f;
    num = fmaf(v000, dr0 * dr1 * dr2, num);
    num = fmaf(v001, dr0 * dr1 * dl2, num);
    num = fmaf(v010, dr0 * dl1 * dr2, num);
    num = fmaf(v011, dr0 * dl1 * dl2, num);
    num = fmaf(v100, dl0 * dr1 * dr2, num);
    num = fmaf(v101, dl0 * dr1 * dl2, num);
    num = fmaf(v110, dl0 * dl1 * dr2, num);
    num = fmaf(v111, dl0 * dl1 * dl2, num);
    float denom = (dl0 + dr0) * (dl1 + dr1) * (dl2 + dr2);

    out[i] = num / denom;
}

extern "C" void kernel_launch(void* const* d_in, const int* in_sizes, int n_in,
                              void* d_out, int out_size)
{
    const float* x0 = (const float*)d_in[0];
    const float* x1 = (const float*)d_in[1];
    const float* x2 = (const float*)d_in[2];
    const float* values = (const float*)d_in[6];
    float* out = (float*)d_out;

    int n = in_sizes[0];
    int blocks = (n + 255) / 256;
    rgi_kernel<<<blocks, 256>>>(x0, x1, x2, values, out, n);
}

// round 10
// speedup vs baseline: 2.6238x; 1.3497x over previous
#include <cuda_runtime.h>

#define GRIDN 256
#define STEP  (1.0f / 255.0f)

// Exact bracket (reference searchsorted-right + clamp/distance semantics)
// for the linspace grid p[i] = i*STEP. Pure ALU/FMA, no memory.
__device__ __forceinline__ void bracketA(float x, int& il, int& ir,
                                         float& dl, float& dr)
{
    int g = (int)floorf(x * 255.0f) + 1;
    g = max(0, min(g, GRIDN));
    while (g < GRIDN && (float)g * STEP <= x) g++;
    while (g > 0 && (float)(g - 1) * STEP > x) g--;
    ir = min(g, GRIDN - 1);
    il = max(ir - 1, 0);
    dl = fmaxf(x - (float)il * STEP, 0.0f);
    dr = fmaxf((float)ir * STEP - x, 0.0f);
    if (dl == 0.0f && dr == 0.0f) { dl = 1.0f; dr = 1.0f; }
}

__global__ __launch_bounds__(256)
void rgi_kernel(const float* __restrict__ x0, const float* __restrict__ x1,
                const float* __restrict__ x2,
                const float* __restrict__ values,
                float* __restrict__ out, int n)
{
    int i = blockIdx.x * blockDim.x + threadIdx.x;
    if (i >= n) return;

    // Streaming reads: evict-first so `values` keeps its L2 residency.
    float q0 = __ldcs(x0 + i);
    float q1 = __ldcs(x1 + i);
    float q2 = __ldcs(x2 + i);

    int il0, ir0, il1, ir1, il2, ir2;
    float dl0, dr0, dl1, dr1, dl2, dr2;
    bracketA(q0, il0, ir0, dl0, dr0);
    bracketA(q1, il1, ir1, dl1, dr1);
    bracketA(q2, il2, ir2, dl2, dr2);

    // 32-bit row bases (256^3 < 2^31); each is a multiple of 256 floats,
    // so (base + even) is 8B-aligned for float2 loads.
    int bll = (il0 * GRIDN + il1) * GRIDN;
    int blr = (il0 * GRIDN + ir1) * GRIDN;
    int brl = (ir0 * GRIDN + il1) * GRIDN;
    int brr = (ir0 * GRIDN + ir1) * GRIDN;

    // k-pair merged into one aligned LDG.64 per row.
    // e = il2 & ~1. Even il2: f = (v[il2], v[il2+1]) covers both corners
    //   (low-clamp il2==ir2==0 selects f.x twice -- correct).
    // Odd il2: f = (v[il2-1], v[il2]); ir2 = il2+1 needs one extra scalar
    //   (il2 odd => il2 > 0 => no clamp case, ir2 == il2+1 guaranteed).
    const int e   = il2 & ~1;
    const bool odd = (il2 & 1);
    const bool rhi = (ir2 & 1);   // even-il2 case: ir2 odd -> f.y, else f.x

    float2 fll = __ldg((const float2*)(values + bll + e));
    float2 flr = __ldg((const float2*)(values + blr + e));
    float2 frl = __ldg((const float2*)(values + brl + e));
    float2 frr = __ldg((const float2*)(values + brr + e));

    float v000 = odd ? fll.y : fll.x;
    float v010 = odd ? flr.y : flr.x;
    float v100 = odd ? frl.y : frl.x;
    float v110 = odd ? frr.y : frr.x;

    float v001, v011, v101, v111;
    if (odd) {
        v001 = __ldg(values + bll + il2 + 1);
        v011 = __ldg(values + blr + il2 + 1);
        v101 = __ldg(values + brl + il2 + 1);
        v111 = __ldg(values + brr + il2 + 1);
    } else {
        v001 = rhi ? fll.y : fll.x;
        v011 = rhi ? flr.y : flr.x;
        v101 = rhi ? frl.y : frl.x;
        v111 = rhi ? frr.y : frr.x;
    }

    // Corner weight = product of OPPOSITE-side distances (reference semantics).
    float num = 0.0f;
    num = fmaf(v000, dr0 * dr1 * dr2, num);
    num = fmaf(v001, dr0 * dr1 * dl2, num);
    num = fmaf(v010, dr0 * dl1 * dr2, num);
    num = fmaf(v011, dr0 * dl1 * dl2, num);
    num = fmaf(v100, dl0 * dr1 * dr2, num);
    num = fmaf(v101, dl0 * dr1 * dl2, num);
    num = fmaf(v110, dl0 * dl1 * dr2, num);
    num = fmaf(v111, dl0 * dl1 * dl2, num);
    float denom = (dl0 + dr0) * (dl1 + dr1) * (dl2 + dr2);

    out[i] = num / denom;
}

extern "C" void kernel_launch(void* const* d_in, const int* in_sizes, int n_in,
                              void* d_out, int out_size)
{
    const float* x0 = (const float*)d_in[0];
    const float* x1 = (const float*)d_in[1];
    const float* x2 = (const float*)d_in[2];
    const float* values = (const float*)d_in[6];
    float* out = (float*)d_out;

    int n = in_sizes[0];
    int blocks = (n + 255) / 256;
    rgi_kernel<<<blocks, 256>>>(x0, x1, x2, values, out, n);
}